// round 15
// baseline (speedup 1.0000x reference)
#include <cuda_runtime.h>
#include <cstdint>

// Problem constants (fixed shapes)
#define BB 2
#define NN 16384
#define MM 8192
#define NPTS (2*NN + 2*MM)        // 49152 points total (both sets, both batches)

// Spatial grid
#define G 32
#define G3 (G*G*G)                // 32768 cells
#define OFFSTRIDE (G3 + 4)        // int4-aligned row stride for offsets
#define H 0.25f
#define INVH 4.0f
#define ORIG (-4.0f)

#define NEG_BIG -3.0e38f

// ---------------- scratch (device globals) -----------------------------------
// slots: 0 = n-set b0, 1 = n-set b1, 2 = m-set b0, 3 = m-set b1
__device__ int    g_cnt[4][G3];          // per-cell counts (memset to 0 each launch)
__device__ int    g_off_raw[4 * OFFSTRIDE]; // exclusive prefix offsets (+ total at [G3])
__device__ int2   g_cellrank[NPTS];      // per point: (cell, rank-in-cell)
__device__ float4 g_sorted[NPTS];        // cell-sorted points; .w = original index bits
__device__ float  g_md[NPTS];            // per original point: min dist^2 to opposite set
__device__ float4 g_part[128];           // reduce partials {s0, s1, s2, wm_local}
__device__ unsigned int g_done = 0;      // completion counter (self-resetting)

// Order-preserving float<->int encoding (for weight max via s32 redux).
__device__ __forceinline__ int encf(float f) {
    int i = __float_as_int(f);
    return (i >= 0) ? i : (i ^ 0x7FFFFFFF);
}
__device__ __forceinline__ float decf(int k) {
    return __int_as_float((k >= 0) ? k : (k ^ 0x7FFFFFFF));
}
__device__ __forceinline__ int redux_maxi(int v) {
    int r; asm("redux.sync.max.s32 %0, %1, 0xffffffff;" : "=r"(r) : "r"(v)); return r;
}

// point index space: [0, 2*NN) = n points (i = b*NN + n); [2*NN, NPTS) = m points.
__device__ __forceinline__ const float* point_ptr(int i, const float* p1, const float* p2) {
    return (i < 2 * NN) ? (p1 + (size_t)i * 3) : (p2 + (size_t)(i - 2 * NN) * 3);
}
__device__ __forceinline__ int point_slot(int i) {
    return (i < 2 * NN) ? (i >> 14) : (2 + ((i - 2 * NN) >> 13));
}
__device__ __forceinline__ int slot_base(int s) {
    return (s < 2) ? s * NN : 2 * NN + (s - 2) * MM;
}
__device__ __forceinline__ int cell_coord(float v) {
    return min(max(__float2int_rd((v - ORIG) * INVH), 0), G - 1);
}

// ---------------- kernel 1: count points per cell -----------------------------
__global__ void k_count(const float* __restrict__ p1, const float* __restrict__ p2) {
    int i = blockIdx.x * 256 + threadIdx.x;          // 192*256 = NPTS exactly
    const float* p = point_ptr(i, p1, p2);
    float x = p[0], y = p[1], z = p[2];
    int cell = (cell_coord(z) * G + cell_coord(y)) * G + cell_coord(x);
    int slot = point_slot(i);
    int rank = atomicAdd(&g_cnt[slot][cell], 1);
    g_cellrank[i] = make_int2(cell, rank);
}

// ---------------- kernel 2: exclusive prefix scan per slot --------------------
__global__ void __launch_bounds__(1024) k_scan() {
    const int slot = blockIdx.x;                     // 4 blocks
    const int tid = threadIdx.x, lane = tid & 31, wid = tid >> 5;
    __shared__ int swarp[32];
    const int PER = G3 / 1024;                       // 32 cells per thread
    const int4* cin = (const int4*)&g_cnt[slot][tid * PER];

    int sum = 0;
#pragma unroll
    for (int k = 0; k < PER / 4; k++) {
        int4 v = cin[k];
        sum += v.x + v.y + v.z + v.w;
    }
    int inc = sum;
#pragma unroll
    for (int o = 1; o < 32; o <<= 1) {
        int t = __shfl_up_sync(0xffffffffu, inc, o);
        if (lane >= o) inc += t;
    }
    if (lane == 31) swarp[wid] = inc;
    __syncthreads();
    if (wid == 0) {
        int u = swarp[lane];
#pragma unroll
        for (int o = 1; o < 32; o <<= 1) {
            int t = __shfl_up_sync(0xffffffffu, u, o);
            if (lane >= o) u += t;
        }
        swarp[lane] = u;
    }
    __syncthreads();
    int run = inc - sum + (wid > 0 ? swarp[wid - 1] : 0);   // exclusive prefix
    int4* cout = (int4*)&g_off_raw[slot * OFFSTRIDE + tid * PER];
#pragma unroll
    for (int k = 0; k < PER / 4; k++) {
        int4 v = cin[k];
        int4 o;
        o.x = run; run += v.x;
        o.y = run; run += v.y;
        o.z = run; run += v.z;
        o.w = run; run += v.w;
        cout[k] = o;
    }
    if (tid == 1023) g_off_raw[slot * OFFSTRIDE + G3] = run; // total
}

// ---------------- kernel 3: scatter into cell-sorted order --------------------
__global__ void k_scatter(const float* __restrict__ p1, const float* __restrict__ p2) {
    int i = blockIdx.x * 256 + threadIdx.x;
    const float* p = point_ptr(i, p1, p2);
    int slot = point_slot(i);
    int2 cr = g_cellrank[i];
    int pos = g_off_raw[slot * OFFSTRIDE + cr.x] + cr.y;
    g_sorted[slot_base(slot) + pos] =
        make_float4(p[0], p[1], p[2], __int_as_float(i));   // stash original index
}

// ---------------- kernel 4: expanding-box nearest-neighbor query --------------
// Iterates over the SORTED array so warps are spatially coherent.
// Termination bound: any point outside Chebyshev box(r) is at distance >= r*H
// (holds also for boundary-clamped/overshooting points; see per-axis argument).
__global__ void k_query() {
    int i = blockIdx.x * 256 + threadIdx.x;          // over NPTS sorted entries
    float4 q4 = g_sorted[i];
    float qx = q4.x, qy = q4.y, qz = q4.z;
    int orig = __float_as_int(q4.w);
    // my slot from sorted position; target = opposite set, same batch
    int myslot = (i < NN) ? 0 : (i < 2 * NN) ? 1 : (i < 2 * NN + MM) ? 2 : 3;
    int tslot = myslot ^ 2;
    const int* off = &g_off_raw[tslot * OFFSTRIDE];
    const float4* pts = &g_sorted[slot_base(tslot)];

    int cx = cell_coord(qx), cy = cell_coord(qy), cz = cell_coord(qz);
    float best = 3.0e38f;
    for (int r = 1; r <= G; r++) {
        int zlo = max(cz - r, 0), zhi = min(cz + r, G - 1);
        int ylo = max(cy - r, 0), yhi = min(cy + r, G - 1);
        int xlo = max(cx - r, 0), xhi = min(cx + r, G - 1);
        for (int z = zlo; z <= zhi; z++) {
            for (int y = ylo; y <= yhi; y++) {
                int rowc = (z * G + y) * G;
                int o0 = off[rowc + xlo];
                int o1 = off[rowc + xhi + 1];        // end of cell rowc+xhi
                for (int k = o0; k < o1; k++) {
                    float4 pt = pts[k];
                    float dx = qx - pt.x, dy = qy - pt.y, dz = qz - pt.z;
                    float d2 = fmaf(dx, dx, fmaf(dy, dy, dz * dz));
                    best = fminf(best, d2);
                }
            }
        }
        float bnd = (float)r * H;
        if (bnd * bnd > best) break;                 // exact-min safe termination
    }
    g_md[orig] = best;
}

// ---------------- kernel 5: softmax-weighted reduce + fused final -------------
__global__ void __launch_bounds__(256) k_reduce(const float* __restrict__ w,
                                                float* __restrict__ out) {
    const int blk = blockIdx.x;               // 128 blocks (64 per batch)
    const int b = blk >> 6;
    const int idx = blk & 63;
    const int tid = threadIdx.x;
    const int lane = tid & 31, wid = tid >> 5;

    __shared__ float sA[8], sB[8], sC[8];
    __shared__ int swx[8];
    __shared__ float sa[256], sb[256], sc[256];

    const int gn = b * NN + idx * 256 + tid;  // one n per thread
    float wv = w[gn];
    float md1 = g_md[gn];
    float md2 = 0.f;
    if (tid < 128) md2 = g_md[2 * NN + b * MM + idx * 128 + tid];

    // block-local weight max (softmax shift-invariance; rescaled in combine)
    int te = redux_maxi(encf(wv));
    if (lane == 0) swx[wid] = te;
    __syncthreads();
    int wme = swx[0];
#pragma unroll
    for (int k = 1; k < 8; k++) wme = max(wme, swx[k]);
    float wm = decf(wme);

    float e = expf(wv - wm);
    float s0 = e;
    float s1 = e * md1;
    float s2 = md2;

#pragma unroll
    for (int o = 16; o > 0; o >>= 1) {
        s0 += __shfl_xor_sync(0xffffffffu, s0, o);
        s1 += __shfl_xor_sync(0xffffffffu, s1, o);
        s2 += __shfl_xor_sync(0xffffffffu, s2, o);
    }
    if (lane == 0) { sA[wid] = s0; sB[wid] = s1; sC[wid] = s2; }
    __syncthreads();

    __shared__ int last;
    if (tid == 0) {
        float a = 0.f, bb = 0.f, c = 0.f;
#pragma unroll
        for (int k = 0; k < 8; k++) { a += sA[k]; bb += sB[k]; c += sC[k]; }
        float4 r; r.x = a; r.y = bb; r.z = c; r.w = wm;
        g_part[blk] = r;
        __threadfence();
        unsigned int prev = atomicAdd(&g_done, 1u);
        last = (prev == 127u) ? 1 : 0;
    }
    __syncthreads();
    if (!last) return;
    __threadfence();

    // last block: deterministic fixed-order combine of 128 partials
    float4 gp = make_float4(0.f, 0.f, 0.f, NEG_BIG);
    if (tid < 128) {
        volatile float4* vp = (volatile float4*)&g_part[tid];
        gp.x = vp->x; gp.y = vp->y; gp.z = vp->z; gp.w = vp->w;
    }
    // phase 1: global weight max per batch half
    sa[tid] = gp.w;
    __syncthreads();
    for (int st = 32; st > 0; st >>= 1) {
        if (tid < 128 && (tid & 63) < st) sa[tid] = fmaxf(sa[tid], sa[tid + st]);
        __syncthreads();
    }
    float wmg = (tid < 128) ? sa[(tid >> 6) << 6] : 0.f;
    __syncthreads();
    // phase 2: rescale local-softmax partials to the global max and reduce
    float c0 = 0.f, c1 = 0.f, c2 = 0.f;
    if (tid < 128) {
        float s = expf(gp.w - wmg);
        c0 = gp.x * s; c1 = gp.y * s; c2 = gp.z;
    }
    sa[tid] = c0; sb[tid] = c1; sc[tid] = c2;
    __syncthreads();
    for (int st = 32; st > 0; st >>= 1) {
        if (tid < 128 && (tid & 63) < st) {
            sa[tid] += sa[tid + st];
            sb[tid] += sb[tid + st];
            sc[tid] += sc[tid + st];
        }
        __syncthreads();
    }
    if (tid == 0) {
        float loss = 0.f;
        loss += sb[0]  / sa[0]  + sc[0]  / (float)MM;
        loss += sb[64] / sa[64] + sc[64] / (float)MM;
        out[0] = loss / (float)BB;
        g_done = 0;                           // reset for graph replay
    }
}

// ---------------- launch -----------------------------------------------------
extern "C" void kernel_launch(void* const* d_in, const int* in_sizes, int n_in,
                              void* d_out, int out_size) {
    const float* points1 = (const float*)d_in[0];   // (2,16384,3)
    const float* points2 = (const float*)d_in[1];   // (2,8192,3)
    const float* weights = (const float*)d_in[2];   // (2,16384)
    float* out = (float*)d_out;

    void* pc;
    cudaGetSymbolAddress(&pc, g_cnt);
    cudaMemsetAsync(pc, 0, sizeof(int) * 4 * G3);   // zero counts (graph-capturable)

    k_count  <<<NPTS / 256, 256>>>(points1, points2);
    k_scan   <<<4, 1024>>>();
    k_scatter<<<NPTS / 256, 256>>>(points1, points2);
    k_query  <<<NPTS / 256, 256>>>();
    k_reduce <<<128, 256>>>(weights, out);
}

// round 16
// speedup vs baseline: 1.4712x; 1.4712x over previous
#include <cuda_runtime.h>
#include <cstdint>

// Problem constants (fixed shapes)
#define BB 2
#define NN 16384
#define MM 8192
#define NPTS (2*NN + 2*MM)        // 49152 points total (both sets, both batches)

// Spatial grid
#define G 32
#define G3 (G*G*G)                // 32768 cells
#define OFFSTRIDE (G3 + 4)        // int4-aligned row stride for offsets
#define H 0.25f
#define INVH 4.0f
#define ORIG (-4.0f)

// Query split: 4 lanes cooperate on one query
#define SUB 4

#define NEG_BIG -3.0e38f

// ---------------- scratch (device globals) -----------------------------------
// slots: 0 = n-set b0, 1 = n-set b1, 2 = m-set b0, 3 = m-set b1
__device__ int    g_cnt[4][G3];          // per-cell counts (zeroed by k_scatter for next replay)
__device__ int    g_off_raw[4 * OFFSTRIDE]; // exclusive prefix offsets (+ total at [G3])
__device__ int2   g_cellrank[NPTS];      // per point: (cell, rank-in-cell)
__device__ float4 g_sorted[NPTS];        // cell-sorted points; .w = original index bits
__device__ float  g_md[NPTS];            // per original point: min dist^2 to opposite set
__device__ float4 g_part[128];           // reduce partials {s0, s1, s2, wm_local}
__device__ unsigned int g_done = 0;      // completion counter (self-resetting)

// Order-preserving float<->int encoding (for weight max via s32 redux).
__device__ __forceinline__ int encf(float f) {
    int i = __float_as_int(f);
    return (i >= 0) ? i : (i ^ 0x7FFFFFFF);
}
__device__ __forceinline__ float decf(int k) {
    return __int_as_float((k >= 0) ? k : (k ^ 0x7FFFFFFF));
}
__device__ __forceinline__ int redux_maxi(int v) {
    int r; asm("redux.sync.max.s32 %0, %1, 0xffffffff;" : "=r"(r) : "r"(v)); return r;
}

// point index space: [0, 2*NN) = n points (i = b*NN + n); [2*NN, NPTS) = m points.
__device__ __forceinline__ const float* point_ptr(int i, const float* p1, const float* p2) {
    return (i < 2 * NN) ? (p1 + (size_t)i * 3) : (p2 + (size_t)(i - 2 * NN) * 3);
}
__device__ __forceinline__ int point_slot(int i) {
    return (i < 2 * NN) ? (i >> 14) : (2 + ((i - 2 * NN) >> 13));
}
__device__ __forceinline__ int slot_base(int s) {
    return (s < 2) ? s * NN : 2 * NN + (s - 2) * MM;
}
__device__ __forceinline__ int cell_coord(float v) {
    return min(max(__float2int_rd((v - ORIG) * INVH), 0), G - 1);
}

// ---------------- kernel 1: count points per cell -----------------------------
__global__ void k_count(const float* __restrict__ p1, const float* __restrict__ p2) {
    int i = blockIdx.x * 256 + threadIdx.x;          // 192*256 = NPTS exactly
    const float* p = point_ptr(i, p1, p2);
    float x = p[0], y = p[1], z = p[2];
    int cell = (cell_coord(z) * G + cell_coord(y)) * G + cell_coord(x);
    int slot = point_slot(i);
    int rank = atomicAdd(&g_cnt[slot][cell], 1);
    g_cellrank[i] = make_int2(cell, rank);
}

// ---------------- kernel 2: exclusive prefix scan per slot --------------------
__global__ void __launch_bounds__(1024) k_scan() {
    const int slot = blockIdx.x;                     // 4 blocks
    const int tid = threadIdx.x, lane = tid & 31, wid = tid >> 5;
    __shared__ int swarp[32];
    const int PER = G3 / 1024;                       // 32 cells per thread
    const int4* cin = (const int4*)&g_cnt[slot][tid * PER];

    int sum = 0;
#pragma unroll
    for (int k = 0; k < PER / 4; k++) {
        int4 v = cin[k];
        sum += v.x + v.y + v.z + v.w;
    }
    int inc = sum;
#pragma unroll
    for (int o = 1; o < 32; o <<= 1) {
        int t = __shfl_up_sync(0xffffffffu, inc, o);
        if (lane >= o) inc += t;
    }
    if (lane == 31) swarp[wid] = inc;
    __syncthreads();
    if (wid == 0) {
        int u = swarp[lane];
#pragma unroll
        for (int o = 1; o < 32; o <<= 1) {
            int t = __shfl_up_sync(0xffffffffu, u, o);
            if (lane >= o) u += t;
        }
        swarp[lane] = u;
    }
    __syncthreads();
    int run = inc - sum + (wid > 0 ? swarp[wid - 1] : 0);   // exclusive prefix
    int4* cout = (int4*)&g_off_raw[slot * OFFSTRIDE + tid * PER];
#pragma unroll
    for (int k = 0; k < PER / 4; k++) {
        int4 v = cin[k];
        int4 o;
        o.x = run; run += v.x;
        o.y = run; run += v.y;
        o.z = run; run += v.z;
        o.w = run; run += v.w;
        cout[k] = o;
    }
    if (tid == 1023) g_off_raw[slot * OFFSTRIDE + G3] = run; // total
}

// ---------------- kernel 3: scatter + zero counts for next replay -------------
__global__ void k_scatter(const float* __restrict__ p1, const float* __restrict__ p2) {
    int i = blockIdx.x * 256 + threadIdx.x;
    const float* p = point_ptr(i, p1, p2);
    int slot = point_slot(i);
    int2 cr = g_cellrank[i];
    int pos = g_off_raw[slot * OFFSTRIDE + cr.x] + cr.y;
    g_sorted[slot_base(slot) + pos] =
        make_float4(p[0], p[1], p[2], __int_as_float(i));   // stash original index

    // zero g_cnt for the next graph replay (replaces the memset launch)
    int* cz = (int*)g_cnt;
#pragma unroll
    for (int j = i; j < 4 * G3; j += NPTS) cz[j] = 0;
}

// ---------------- kernel 4: expanding-box NN query, 4 lanes per query ---------
// Lane sub of each aligned 4-lane group scans rows j === sub (mod 4) of the
// Chebyshev box(r); group-combined best via 2 shfl_xor. Termination bound:
// any point outside box(r) is at distance >= r*H (exact-min safe).
__global__ void k_query() {
    int gid = blockIdx.x * 256 + threadIdx.x;        // NPTS*SUB threads
    int i   = gid >> 2;                              // query = sorted index
    int sub = gid & 3;
    float4 q4 = g_sorted[i];
    float qx = q4.x, qy = q4.y, qz = q4.z;
    int orig = __float_as_int(q4.w);
    int myslot = (i < NN) ? 0 : (i < 2 * NN) ? 1 : (i < 2 * NN + MM) ? 2 : 3;
    int tslot = myslot ^ 2;
    const int* off = &g_off_raw[tslot * OFFSTRIDE];
    const float4* pts = &g_sorted[slot_base(tslot)];

    int cx = cell_coord(qx), cy = cell_coord(qy), cz = cell_coord(qz);
    float best = 3.0e38f;
    for (int r = 1; r <= G; r++) {
        int side = 2 * r + 1;
        int R = side * side;                         // rows (z,y) in the box
        int xlo = max(cx - r, 0), xhi = min(cx + r, G - 1);
        for (int j = sub; j < R; j += SUB) {
            int z = cz + j / side - r;
            int y = cy + j % side - r;
            if ((unsigned)z >= G || (unsigned)y >= G) continue;
            int rowc = (z * G + y) * G;
            int o0 = off[rowc + xlo];
            int o1 = off[rowc + xhi + 1];            // end of cell rowc+xhi
            for (int k = o0; k < o1; k++) {
                float4 pt = pts[k];
                float dx = qx - pt.x, dy = qy - pt.y, dz = qz - pt.z;
                float d2 = fmaf(dx, dx, fmaf(dy, dy, dz * dz));
                best = fminf(best, d2);
            }
        }
        // combine across the aligned 4-lane group
        best = fminf(best, __shfl_xor_sync(0xffffffffu, best, 1));
        best = fminf(best, __shfl_xor_sync(0xffffffffu, best, 2));
        float bnd = (float)r * H;
        if (bnd * bnd > best) break;                 // group-uniform decision
    }
    if (sub == 0) g_md[orig] = best;
}

// ---------------- kernel 5: softmax-weighted reduce + fused final -------------
__global__ void __launch_bounds__(256) k_reduce(const float* __restrict__ w,
                                                float* __restrict__ out) {
    const int blk = blockIdx.x;               // 128 blocks (64 per batch)
    const int b = blk >> 6;
    const int idx = blk & 63;
    const int tid = threadIdx.x;
    const int lane = tid & 31, wid = tid >> 5;

    __shared__ float sA[8], sB[8], sC[8];
    __shared__ int swx[8];
    __shared__ float sa[256], sb[256], sc[256];

    const int gn = b * NN + idx * 256 + tid;  // one n per thread
    float wv = w[gn];
    float md1 = g_md[gn];
    float md2 = 0.f;
    if (tid < 128) md2 = g_md[2 * NN + b * MM + idx * 128 + tid];

    // block-local weight max (softmax shift-invariance; rescaled in combine)
    int te = redux_maxi(encf(wv));
    if (lane == 0) swx[wid] = te;
    __syncthreads();
    int wme = swx[0];
#pragma unroll
    for (int k = 1; k < 8; k++) wme = max(wme, swx[k]);
    float wm = decf(wme);

    float e = expf(wv - wm);
    float s0 = e;
    float s1 = e * md1;
    float s2 = md2;

#pragma unroll
    for (int o = 16; o > 0; o >>= 1) {
        s0 += __shfl_xor_sync(0xffffffffu, s0, o);
        s1 += __shfl_xor_sync(0xffffffffu, s1, o);
        s2 += __shfl_xor_sync(0xffffffffu, s2, o);
    }
    if (lane == 0) { sA[wid] = s0; sB[wid] = s1; sC[wid] = s2; }
    __syncthreads();

    __shared__ int last;
    if (tid == 0) {
        float a = 0.f, bb = 0.f, c = 0.f;
#pragma unroll
        for (int k = 0; k < 8; k++) { a += sA[k]; bb += sB[k]; c += sC[k]; }
        float4 r; r.x = a; r.y = bb; r.z = c; r.w = wm;
        g_part[blk] = r;
        __threadfence();
        unsigned int prev = atomicAdd(&g_done, 1u);
        last = (prev == 127u) ? 1 : 0;
    }
    __syncthreads();
    if (!last) return;
    __threadfence();

    // last block: deterministic fixed-order combine of 128 partials
    float4 gp = make_float4(0.f, 0.f, 0.f, NEG_BIG);
    if (tid < 128) {
        volatile float4* vp = (volatile float4*)&g_part[tid];
        gp.x = vp->x; gp.y = vp->y; gp.z = vp->z; gp.w = vp->w;
    }
    // phase 1: global weight max per batch half
    sa[tid] = gp.w;
    __syncthreads();
    for (int st = 32; st > 0; st >>= 1) {
        if (tid < 128 && (tid & 63) < st) sa[tid] = fmaxf(sa[tid], sa[tid + st]);
        __syncthreads();
    }
    float wmg = (tid < 128) ? sa[(tid >> 6) << 6] : 0.f;
    __syncthreads();
    // phase 2: rescale local-softmax partials to the global max and reduce
    float c0 = 0.f, c1 = 0.f, c2 = 0.f;
    if (tid < 128) {
        float s = expf(gp.w - wmg);
        c0 = gp.x * s; c1 = gp.y * s; c2 = gp.z;
    }
    sa[tid] = c0; sb[tid] = c1; sc[tid] = c2;
    __syncthreads();
    for (int st = 32; st > 0; st >>= 1) {
        if (tid < 128 && (tid & 63) < st) {
            sa[tid] += sa[tid + st];
            sb[tid] += sb[tid + st];
            sc[tid] += sc[tid + st];
        }
        __syncthreads();
    }
    if (tid == 0) {
        float loss = 0.f;
        loss += sb[0]  / sa[0]  + sc[0]  / (float)MM;
        loss += sb[64] / sa[64] + sc[64] / (float)MM;
        out[0] = loss / (float)BB;
        g_done = 0;                           // reset for graph replay
    }
}

// ---------------- launch -----------------------------------------------------
extern "C" void kernel_launch(void* const* d_in, const int* in_sizes, int n_in,
                              void* d_out, int out_size) {
    const float* points1 = (const float*)d_in[0];   // (2,16384,3)
    const float* points2 = (const float*)d_in[1];   // (2,8192,3)
    const float* weights = (const float*)d_in[2];   // (2,16384)
    float* out = (float*)d_out;

    k_count  <<<NPTS / 256, 256>>>(points1, points2);
    k_scan   <<<4, 1024>>>();
    k_scatter<<<NPTS / 256, 256>>>(points1, points2);
    k_query  <<<NPTS * SUB / 256, 256>>>();
    k_reduce <<<128, 256>>>(weights, out);
}